// round 2
// baseline (speedup 1.0000x reference)
#include <cuda_runtime.h>
#include <math.h>

// ---------------------------------------------------------------------------
// VDP attention: mu/sigma propagation through LN -> QKV -> attention -> out.
// B=4, N=1024, D=1024, H=16, Dh=64. All fp32 SIMT for round 1.
// ---------------------------------------------------------------------------

#define B_ 4
#define N_ 1024
#define D_ 1024
#define H_ 16
#define DH_ 64
#define M_ (B_ * N_)       /* 4096 rows */
#define QKV_ (3 * D_)      /* 3072 */
#define BH_ (B_ * H_)      /* 64 */
#define SCALE_ 0.125f      /* 64^-0.5 */

// ------------------------- scratch (static device) -------------------------
__device__ float g_mu_n [M_ * D_];
__device__ float g_sg_n [M_ * D_];
__device__ float g_m2s  [M_ * D_];          // mu_n^2 + sigma_n
__device__ float g_Wqkv_sig[QKV_ * D_];
__device__ float g_Wqkv_mu2[QKV_ * D_];
__device__ float g_Wout_sig[D_ * D_];
__device__ float g_Wout_mu2[D_ * D_];
__device__ float g_mu_qkv[M_ * QKV_];
__device__ float g_sg_qkv[M_ * QKV_];
__device__ float g_mu_dots[BH_ * N_ * N_];  // 268 MB, becomes attn in-place
__device__ float g_sg_dots[BH_ * N_ * N_];
__device__ float g_mu_o [M_ * D_];
__device__ float g_sg_o [M_ * D_];
__device__ float g_m2s_o[M_ * D_];          // mu_o^2 + sg_o

// ------------------------------ prep weights -------------------------------
__device__ __forceinline__ float softplusf(float x) {
    return fmaxf(x, 0.0f) + log1pf(expf(-fabsf(x)));
}

__global__ void prep_weights_kernel(const float* __restrict__ Wqkv_mu,
                                    const float* __restrict__ Wqkv_raw,
                                    const float* __restrict__ Wout_mu,
                                    const float* __restrict__ Wout_raw) {
    int i = blockIdx.x * blockDim.x + threadIdx.x;
    const int nq = QKV_ * D_;
    if (i < nq) {
        float w = Wqkv_mu[i];
        g_Wqkv_mu2[i] = w * w;
        g_Wqkv_sig[i] = softplusf(Wqkv_raw[i]);
    } else {
        int j = i - nq;
        if (j < D_ * D_) {
            float w = Wout_mu[j];
            g_Wout_mu2[j] = w * w;
            g_Wout_sig[j] = softplusf(Wout_raw[j]);
        }
    }
}

// -------------------------------- layernorm --------------------------------
__global__ void layernorm_kernel(const float* __restrict__ mu,
                                 const float* __restrict__ sigma,
                                 const float* __restrict__ gamma,
                                 const float* __restrict__ beta) {
    const int row = blockIdx.x;           // 0..4095
    const int t   = threadIdx.x;          // 256 threads, 4 elems each
    const float4* mrow = (const float4*)(mu + (size_t)row * D_);
    float4 m = mrow[t];

    float s  = m.x + m.y + m.z + m.w;
    float sq = m.x * m.x + m.y * m.y + m.z * m.z + m.w * m.w;

    __shared__ float red[256];
    red[t] = s; __syncthreads();
    #pragma unroll
    for (int o = 128; o > 0; o >>= 1) { if (t < o) red[t] += red[t + o]; __syncthreads(); }
    float mean = red[0] * (1.0f / D_);
    __syncthreads();
    red[t] = sq; __syncthreads();
    #pragma unroll
    for (int o = 128; o > 0; o >>= 1) { if (t < o) red[t] += red[t + o]; __syncthreads(); }
    float var = red[0] * (1.0f / D_) - mean * mean;
    float inv = rsqrtf(var + 1e-5f);

    const float4 sg = ((const float4*)(sigma + (size_t)row * D_))[t];
    const float4 gm = ((const float4*)gamma)[t];
    const float4 bt = ((const float4*)beta)[t];

    float4 mo, so, m2;
    mo.x = (m.x - mean) * inv * gm.x + bt.x;  so.x = sg.x * gm.x * gm.x * inv * inv;  m2.x = fmaf(mo.x, mo.x, so.x);
    mo.y = (m.y - mean) * inv * gm.y + bt.y;  so.y = sg.y * gm.y * gm.y * inv * inv;  m2.y = fmaf(mo.y, mo.y, so.y);
    mo.z = (m.z - mean) * inv * gm.z + bt.z;  so.z = sg.z * gm.z * gm.z * inv * inv;  m2.z = fmaf(mo.z, mo.z, so.z);
    mo.w = (m.w - mean) * inv * gm.w + bt.w;  so.w = sg.w * gm.w * gm.w * inv * inv;  m2.w = fmaf(mo.w, mo.w, so.w);

    ((float4*)g_mu_n)[(size_t)row * 256 + t] = mo;
    ((float4*)g_sg_n)[(size_t)row * 256 + t] = so;
    ((float4*)g_m2s )[(size_t)row * 256 + t] = m2;
}

// ------------------------------ generic C = A * B^T ------------------------
// A[M,K] lda, B[N,K] ldb, C[M,N] ldc. 128x128 tile, BK=8, 256 thr, 8x8/thr.
// Requires M,N %128==0, K %8==0.
template <bool ACCUM>
__global__ void __launch_bounds__(256, 2)
gemm_nt_kernel(float* __restrict__ C, const float* __restrict__ A,
               const float* __restrict__ B, int Kdim, int lda, int ldb, int ldc) {
    __shared__ float As[8][128];
    __shared__ float Bs[8][128];
    const int t  = threadIdx.x;
    const int bm = blockIdx.y * 128;
    const int bn = blockIdx.x * 128;
    const int lrow = t >> 1;
    const int lcol = (t & 1) * 4;
    const float* Ap = A + (size_t)(bm + lrow) * lda + lcol;
    const float* Bp = B + (size_t)(bn + lrow) * ldb + lcol;
    const int tr = (t >> 4) * 8;
    const int tc = (t & 15) * 8;

    float acc[8][8];
    #pragma unroll
    for (int i = 0; i < 8; i++)
        #pragma unroll
        for (int j = 0; j < 8; j++) acc[i][j] = 0.0f;

    float4 av = *(const float4*)Ap;
    float4 bv = *(const float4*)Bp;
    for (int k0 = 8;; k0 += 8) {
        As[lcol + 0][lrow] = av.x; As[lcol + 1][lrow] = av.y;
        As[lcol + 2][lrow] = av.z; As[lcol + 3][lrow] = av.w;
        Bs[lcol + 0][lrow] = bv.x; Bs[lcol + 1][lrow] = bv.y;
        Bs[lcol + 2][lrow] = bv.z; Bs[lcol + 3][lrow] = bv.w;
        __syncthreads();
        const bool more = k0 < Kdim;
        if (more) {
            av = *(const float4*)(Ap + k0);
            bv = *(const float4*)(Bp + k0);
        }
        #pragma unroll
        for (int k = 0; k < 8; k++) {
            float a[8], b[8];
            *(float4*)&a[0] = *(const float4*)&As[k][tr];
            *(float4*)&a[4] = *(const float4*)&As[k][tr + 4];
            *(float4*)&b[0] = *(const float4*)&Bs[k][tc];
            *(float4*)&b[4] = *(const float4*)&Bs[k][tc + 4];
            #pragma unroll
            for (int i = 0; i < 8; i++)
                #pragma unroll
                for (int j = 0; j < 8; j++)
                    acc[i][j] = fmaf(a[i], b[j], acc[i][j]);
        }
        __syncthreads();
        if (!more) break;
    }
    #pragma unroll
    for (int i = 0; i < 8; i++) {
        float* Cp = C + (size_t)(bm + tr + i) * ldc + bn + tc;
        #pragma unroll
        for (int j = 0; j < 8; j += 4) {
            float4 v = make_float4(acc[i][j], acc[i][j + 1], acc[i][j + 2], acc[i][j + 3]);
            if (ACCUM) {
                float4 o = *(const float4*)(Cp + j);
                v.x += o.x; v.y += o.y; v.z += o.z; v.w += o.w;
            }
            *(float4*)(Cp + j) = v;
        }
    }
}

// --------------------------- attention dots --------------------------------
// dots[bh][i][j] = SCALE * sum_d q[b,i,h,d] * k[b,j,h,d]; z<64 -> mu, else sg.
__global__ void __launch_bounds__(256, 2)
dots_kernel() {
    const int z  = blockIdx.z;
    const float* qkv = (z >= BH_) ? g_sg_qkv : g_mu_qkv;
    float* dots      = (z >= BH_) ? g_sg_dots : g_mu_dots;
    const int bh = z & (BH_ - 1);
    const int b  = bh >> 4, h = bh & 15;

    const float* A = qkv + (size_t)b * N_ * QKV_ + h * DH_;   // q, lda=3072
    const float* Bq = A + D_;                                  // k, ldb=3072
    float* C = dots + (size_t)bh * N_ * N_;                    // ldc=1024

    __shared__ float As[8][128];
    __shared__ float Bs[8][128];
    const int t  = threadIdx.x;
    const int bm = blockIdx.y * 128;
    const int bn = blockIdx.x * 128;
    const int lrow = t >> 1;
    const int lcol = (t & 1) * 4;
    const float* Ap = A  + (size_t)(bm + lrow) * QKV_ + lcol;
    const float* Bp = Bq + (size_t)(bn + lrow) * QKV_ + lcol;
    const int tr = (t >> 4) * 8;
    const int tc = (t & 15) * 8;

    float acc[8][8];
    #pragma unroll
    for (int i = 0; i < 8; i++)
        #pragma unroll
        for (int j = 0; j < 8; j++) acc[i][j] = 0.0f;

    float4 av = *(const float4*)Ap;
    float4 bv = *(const float4*)Bp;
    #pragma unroll 1
    for (int k0 = 8;; k0 += 8) {
        As[lcol + 0][lrow] = av.x; As[lcol + 1][lrow] = av.y;
        As[lcol + 2][lrow] = av.z; As[lcol + 3][lrow] = av.w;
        Bs[lcol + 0][lrow] = bv.x; Bs[lcol + 1][lrow] = bv.y;
        Bs[lcol + 2][lrow] = bv.z; Bs[lcol + 3][lrow] = bv.w;
        __syncthreads();
        const bool more = k0 < DH_;
        if (more) {
            av = *(const float4*)(Ap + k0);
            bv = *(const float4*)(Bp + k0);
        }
        #pragma unroll
        for (int k = 0; k < 8; k++) {
            float a[8], b2[8];
            *(float4*)&a[0]  = *(const float4*)&As[k][tr];
            *(float4*)&a[4]  = *(const float4*)&As[k][tr + 4];
            *(float4*)&b2[0] = *(const float4*)&Bs[k][tc];
            *(float4*)&b2[4] = *(const float4*)&Bs[k][tc + 4];
            #pragma unroll
            for (int i = 0; i < 8; i++)
                #pragma unroll
                for (int j = 0; j < 8; j++)
                    acc[i][j] = fmaf(a[i], b2[j], acc[i][j]);
        }
        __syncthreads();
        if (!more) break;
    }
    #pragma unroll
    for (int i = 0; i < 8; i++) {
        float* Cp = C + (size_t)(bm + tr + i) * N_ + bn + tc;
        #pragma unroll
        for (int j = 0; j < 8; j += 4) {
            float4 v = make_float4(acc[i][j] * SCALE_, acc[i][j + 1] * SCALE_,
                                   acc[i][j + 2] * SCALE_, acc[i][j + 3] * SCALE_);
            *(float4*)(Cp + j) = v;
        }
    }
}

// --------------------------------- softmax ---------------------------------
// Row-wise: p = softmax(mu_dots); sg = (p(1-p))^2 * sg_dots. In place.
__global__ void softmax_kernel() {
    const size_t row = blockIdx.x;          // 0..65535 (= bh*1024 + i)
    float* mrow = g_mu_dots + row * N_;
    float* srow = g_sg_dots + row * N_;
    const int t = threadIdx.x;              // 256 threads, 4 elems each

    float4 m = ((const float4*)mrow)[t];
    float lm = fmaxf(fmaxf(m.x, m.y), fmaxf(m.z, m.w));

    __shared__ float red[256];
    red[t] = lm; __syncthreads();
    #pragma unroll
    for (int o = 128; o > 0; o >>= 1) { if (t < o) red[t] = fmaxf(red[t], red[t + o]); __syncthreads(); }
    const float rmax = red[0];
    __syncthreads();

    float4 e;
    e.x = expf(m.x - rmax); e.y = expf(m.y - rmax);
    e.z = expf(m.z - rmax); e.w = expf(m.w - rmax);
    red[t] = e.x + e.y + e.z + e.w; __syncthreads();
    #pragma unroll
    for (int o = 128; o > 0; o >>= 1) { if (t < o) red[t] += red[t + o]; __syncthreads(); }
    const float inv = 1.0f / red[0];

    float4 p;
    p.x = e.x * inv; p.y = e.y * inv; p.z = e.z * inv; p.w = e.w * inv;

    float4 sg = ((const float4*)srow)[t];
    float4 so;
    float jx = p.x * (1.0f - p.x); so.x = jx * jx * sg.x;
    float jy = p.y * (1.0f - p.y); so.y = jy * jy * sg.y;
    float jz = p.z * (1.0f - p.z); so.z = jz * jz * sg.z;
    float jw = p.w * (1.0f - p.w); so.w = jw * jw * sg.w;

    ((float4*)mrow)[t] = p;
    ((float4*)srow)[t] = so;
}

// ------------------------------- P @ V -------------------------------------
// O[b,i,h*64+d] = sum_j attn[bh,i,j] * v[b,j,h,d]. 128x64 tile, BK=16.
__global__ void __launch_bounds__(256, 2)
pv_kernel() {
    const int z = blockIdx.z;
    const float* attn = (z >= BH_) ? g_sg_dots : g_mu_dots;
    const float* qkv  = (z >= BH_) ? g_sg_qkv : g_mu_qkv;
    float* O          = (z >= BH_) ? g_sg_o : g_mu_o;
    const int bh = z & (BH_ - 1);
    const int b = bh >> 4, h = bh & 15;

    const float* A = attn + (size_t)bh * N_ * N_;                  // [i,j] lda=1024
    const float* V = qkv + (size_t)b * N_ * QKV_ + 2 * D_ + h * DH_; // [j,d] ldb=3072
    float* C = O + (size_t)b * N_ * D_ + h * DH_;                  // ldc=1024

    __shared__ float As[16][128];
    __shared__ float Bs[16][64];
    const int t  = threadIdx.x;
    const int bm = blockIdx.y * 128;
    const int ar = t >> 1, ac = (t & 1) * 8;   // A: 128 rows x 16 k, 2 float4/thr
    const int br = t >> 4, bc = (t & 15) * 4;  // B: 16 j x 64 d, 1 float4/thr
    const int tr = (t >> 4) * 8;               // 8 rows
    const int tc = (t & 15) * 4;               // 4 cols

    float acc[8][4];
    #pragma unroll
    for (int i = 0; i < 8; i++)
        #pragma unroll
        for (int j = 0; j < 4; j++) acc[i][j] = 0.0f;

    for (int k0 = 0; k0 < N_; k0 += 16) {
        float4 a0 = *(const float4*)(A + (size_t)(bm + ar) * N_ + k0 + ac);
        float4 a1 = *(const float4*)(A + (size_t)(bm + ar) * N_ + k0 + ac + 4);
        float4 bv = *(const float4*)(V + (size_t)(k0 + br) * QKV_ + bc);
        As[ac + 0][ar] = a0.x; As[ac + 1][ar] = a0.y; As[ac + 2][ar] = a0.z; As[ac + 3][ar] = a0.w;
        As[ac + 4][ar] = a1.x; As[ac + 5][ar] = a1.y; As[ac + 6][ar] = a1.z; As[ac + 7][ar] = a1.w;
        *(float4*)&Bs[br][bc] = bv;
        __syncthreads();
        #pragma unroll
        for (int k = 0; k < 16; k++) {
            float a[8], b2[4];
            *(float4*)&a[0]  = *(const float4*)&As[k][tr];
            *(float4*)&a[4]  = *(const float4*)&As[k][tr + 4];
            *(float4*)&b2[0] = *(const float4*)&Bs[k][tc];
            #pragma unroll
            for (int i = 0; i < 8; i++)
                #pragma unroll
                for (int j = 0; j < 4; j++)
                    acc[i][j] = fmaf(a[i], b2[j], acc[i][j]);
        }
        __syncthreads();
    }
    #pragma unroll
    for (int i = 0; i < 8; i++) {
        float4 v = make_float4(acc[i][0], acc[i][1], acc[i][2], acc[i][3]);
        *(float4*)(C + (size_t)(bm + tr + i) * D_ + tc) = v;
    }
}

// ------------------------------ m2s for output -----------------------------
__global__ void m2so_kernel() {
    int i = blockIdx.x * blockDim.x + threadIdx.x;   // 4M elems
    float mo = g_mu_o[i];
    g_m2s_o[i] = fmaf(mo, mo, g_sg_o[i]);
}

// --------------------------------- launch ----------------------------------
extern "C" void kernel_launch(void* const* d_in, const int* in_sizes, int n_in,
                              void* d_out, int out_size) {
    (void)in_sizes; (void)n_in; (void)out_size;
    const float* mu       = (const float*)d_in[0];
    const float* sigma    = (const float*)d_in[1];
    const float* gamma    = (const float*)d_in[2];
    const float* beta     = (const float*)d_in[3];
    const float* Wqkv_mu  = (const float*)d_in[4];
    const float* Wqkv_raw = (const float*)d_in[5];
    const float* Wout_mu  = (const float*)d_in[6];
    const float* Wout_raw = (const float*)d_in[7];
    float* out = (float*)d_out;

    float *p_mu_n, *p_sg_n, *p_m2s, *p_wqs, *p_wq2, *p_wos, *p_wo2;
    float *p_mu_qkv, *p_sg_qkv, *p_mu_o, *p_sg_o, *p_m2so;
    cudaGetSymbolAddress((void**)&p_mu_n,   g_mu_n);
    cudaGetSymbolAddress((void**)&p_sg_n,   g_sg_n);
    cudaGetSymbolAddress((void**)&p_m2s,    g_m2s);
    cudaGetSymbolAddress((void**)&p_wqs,    g_Wqkv_sig);
    cudaGetSymbolAddress((void**)&p_wq2,    g_Wqkv_mu2);
    cudaGetSymbolAddress((void**)&p_wos,    g_Wout_sig);
    cudaGetSymbolAddress((void**)&p_wo2,    g_Wout_mu2);
    cudaGetSymbolAddress((void**)&p_mu_qkv, g_mu_qkv);
    cudaGetSymbolAddress((void**)&p_sg_qkv, g_sg_qkv);
    cudaGetSymbolAddress((void**)&p_mu_o,   g_mu_o);
    cudaGetSymbolAddress((void**)&p_sg_o,   g_sg_o);
    cudaGetSymbolAddress((void**)&p_m2so,   g_m2s_o);

    // 1. weight transforms
    prep_weights_kernel<<<(QKV_ * D_ + D_ * D_ + 255) / 256, 256>>>(
        Wqkv_mu, Wqkv_raw, Wout_mu, Wout_raw);

    // 2. layernorm (+ mu^2+sigma)
    layernorm_kernel<<<M_, 256>>>(mu, sigma, gamma, beta);

    // 3. QKV projections: mu and sigma (3 GEMMs, 4096x3072x1024)
    dim3 gq(QKV_ / 128, M_ / 128);
    gemm_nt_kernel<false><<<gq, 256>>>(p_mu_qkv, p_mu_n, Wqkv_mu, D_, D_, D_, QKV_);
    gemm_nt_kernel<false><<<gq, 256>>>(p_sg_qkv, p_m2s,  p_wqs,   D_, D_, D_, QKV_);
    gemm_nt_kernel<true ><<<gq, 256>>>(p_sg_qkv, p_sg_n, p_wq2,   D_, D_, D_, QKV_);

    // 4. attention scores (mu & sg), scaled
    dots_kernel<<<dim3(N_ / 128, N_ / 128, 2 * BH_), 256>>>();

    // 5. softmax + variance Jacobian (in place)
    softmax_kernel<<<BH_ * N_, 256>>>();

    // 6. attn @ V (mu & sg), written merged [B*N, H*Dh]
    pv_kernel<<<dim3(1, N_ / 128, 2 * BH_), 256>>>();

    // 7. mu_o^2 + sg_o
    m2so_kernel<<<(M_ * D_) / 256, 256>>>();

    // 8. output projection (3 GEMMs, 4096x1024x1024) -> d_out
    dim3 go(D_ / 128, M_ / 128);
    gemm_nt_kernel<false><<<go, 256>>>(out,            p_mu_o, Wout_mu, D_, D_, D_, D_);
    gemm_nt_kernel<false><<<go, 256>>>(out + M_ * D_,  p_m2so, p_wos,   D_, D_, D_, D_);
    gemm_nt_kernel<true ><<<go, 256>>>(out + M_ * D_,  p_sg_o, p_wo2,   D_, D_, D_, D_);
}

// round 3
// speedup vs baseline: 2.3500x; 2.3500x over previous
#include <cuda_runtime.h>
#include <math.h>
#include <stdint.h>

// ---------------------------------------------------------------------------
// VDP attention, round 2: all GEMMs on tensor cores via tf32 mma.sync.
// B=4, N=1024, D=1024, H=16, Dh=64.
// ---------------------------------------------------------------------------

#define B_ 4
#define N_ 1024
#define D_ 1024
#define H_ 16
#define DH_ 64
#define M_ (B_ * N_)       /* 4096 rows */
#define QKV_ (3 * D_)      /* 3072 */
#define BH_ (B_ * H_)      /* 64 */
#define SCALE_ 0.125f      /* 64^-0.5 */

// ------------------------- scratch (static device) -------------------------
__device__ float g_mu_n [M_ * D_];
__device__ float g_sg_n [M_ * D_];
__device__ float g_m2s  [M_ * D_];          // mu_n^2 + sigma_n
__device__ float g_Wqkv_sig[QKV_ * D_];
__device__ float g_Wqkv_mu2[QKV_ * D_];
__device__ float g_Wout_sig[D_ * D_];
__device__ float g_Wout_mu2[D_ * D_];
__device__ float g_mu_qkv[M_ * QKV_];
__device__ float g_sg_qkv[M_ * QKV_];
__device__ float g_mu_dots[BH_ * N_ * N_];  // becomes attn in place
__device__ float g_sg_dots[BH_ * N_ * N_];
__device__ float g_mu_o [M_ * D_];
__device__ float g_sg_o [M_ * D_];
__device__ float g_m2s_o[M_ * D_];          // mu_o^2 + sg_o

// ------------------------------ tf32 helpers -------------------------------
__device__ __forceinline__ uint32_t f2tf32(float f) {
    uint32_t u;
    asm("cvt.rna.tf32.f32 %0, %1;" : "=r"(u) : "f"(f));
    return u;
}

__device__ __forceinline__ void mma_tf32(float c[4], const uint32_t a[4],
                                         const uint32_t b[2]) {
    asm volatile(
        "mma.sync.aligned.m16n8k8.row.col.f32.tf32.tf32.f32 "
        "{%0,%1,%2,%3},{%4,%5,%6,%7},{%8,%9},{%0,%1,%2,%3};"
        : "+f"(c[0]), "+f"(c[1]), "+f"(c[2]), "+f"(c[3])
        : "r"(a[0]), "r"(a[1]), "r"(a[2]), "r"(a[3]), "r"(b[0]), "r"(b[1]));
}

// ------------------------- tensor-core GEMM core ---------------------------
// C[M,N] (+)= scale * A[M,K] * op(B).  op(B)=B[N,K] (BT=false, "NT") or
// B[K,N] (BT=true, "NN").  Block tile BM x BN, BK=32, 256 threads, 8 warps
// arranged WR x WC (warp tile (BM/WR) x (BN/WC)).
template <int BM, int BN, int WR, int WC, bool ACCUM, bool BT>
__device__ __forceinline__ void gemm_core(float* __restrict__ C,
                                          const float* __restrict__ A,
                                          const float* __restrict__ Bm,
                                          int K, int lda, int ldb, int ldc,
                                          float scale) {
    constexpr int WM = BM / WR, WN = BN / WC;
    constexpr int MT = WM / 16, NT = WN / 8;
    constexpr int PA = 36;                 // smem pitch (floats), conflict-free
    constexpr int PB = BT ? 37 : 36;
    constexpr int NA = BM / 32;            // float4 loads per thread (A tile)
    constexpr int NB = BN / 32;            // float4 loads per thread (B tile)

    __shared__ __align__(16) uint32_t As[BM * PA];
    __shared__ __align__(16) uint32_t Bs[BN * PB];

    const int tid = threadIdx.x;
    const int bm = blockIdx.y * BM, bn = blockIdx.x * BN;
    const int w = tid >> 5, lane = tid & 31;
    const int gr = lane >> 2, tc = lane & 3;
    const int wm = (w / WC) * WM, wn = (w % WC) * WN;

    float acc[MT][NT][4] = {};
    float4 aReg[NA], bReg[NB];

    // ---- global loaders (prefetch into registers) ----
    #pragma unroll
    for (int r = 0; r < NA; r++) {
        int idx = tid + 256 * r;
        aReg[r] = *(const float4*)(A + (size_t)(bm + (idx >> 3)) * lda + (idx & 7) * 4);
    }
    #pragma unroll
    for (int r = 0; r < NB; r++) {
        int idx = tid + 256 * r;
        if (BT) {
            int krow = idx / (BN / 4), n0 = (idx % (BN / 4)) * 4;
            bReg[r] = *(const float4*)(Bm + (size_t)krow * ldb + bn + n0);
        } else {
            bReg[r] = *(const float4*)(Bm + (size_t)(bn + (idx >> 3)) * ldb + (idx & 7) * 4);
        }
    }

    for (int k0 = 32;; k0 += 32) {
        // ---- regs -> smem (tf32 convert) ----
        #pragma unroll
        for (int r = 0; r < NA; r++) {
            int idx = tid + 256 * r;
            uint4 u = make_uint4(f2tf32(aReg[r].x), f2tf32(aReg[r].y),
                                 f2tf32(aReg[r].z), f2tf32(aReg[r].w));
            *(uint4*)&As[(idx >> 3) * PA + (idx & 7) * 4] = u;
        }
        #pragma unroll
        for (int r = 0; r < NB; r++) {
            int idx = tid + 256 * r;
            if (BT) {
                int krow = idx / (BN / 4), n0 = (idx % (BN / 4)) * 4;
                Bs[(n0 + 0) * PB + krow] = f2tf32(bReg[r].x);
                Bs[(n0 + 1) * PB + krow] = f2tf32(bReg[r].y);
                Bs[(n0 + 2) * PB + krow] = f2tf32(bReg[r].z);
                Bs[(n0 + 3) * PB + krow] = f2tf32(bReg[r].w);
            } else {
                uint4 u = make_uint4(f2tf32(bReg[r].x), f2tf32(bReg[r].y),
                                     f2tf32(bReg[r].z), f2tf32(bReg[r].w));
                *(uint4*)&Bs[(idx >> 3) * PB + (idx & 7) * 4] = u;
            }
        }
        __syncthreads();

        const bool more = k0 < K;
        if (more) {
            #pragma unroll
            for (int r = 0; r < NA; r++) {
                int idx = tid + 256 * r;
                aReg[r] = *(const float4*)(A + (size_t)(bm + (idx >> 3)) * lda + (idx & 7) * 4 + k0);
            }
            #pragma unroll
            for (int r = 0; r < NB; r++) {
                int idx = tid + 256 * r;
                if (BT) {
                    int krow = idx / (BN / 4), n0 = (idx % (BN / 4)) * 4;
                    bReg[r] = *(const float4*)(Bm + (size_t)(k0 + krow) * ldb + bn + n0);
                } else {
                    bReg[r] = *(const float4*)(Bm + (size_t)(bn + (idx >> 3)) * ldb + (idx & 7) * 4 + k0);
                }
            }
        }

        // ---- compute: 4 k-steps of 8 ----
        #pragma unroll
        for (int g = 0; g < 4; g++) {
            uint32_t af[MT][4], bf[NT][2];
            #pragma unroll
            for (int i = 0; i < MT; i++) {
                int base = (wm + i * 16 + gr) * PA + g * 8 + tc;
                af[i][0] = As[base];
                af[i][2] = As[base + 4];
                af[i][1] = As[base + 8 * PA];
                af[i][3] = As[base + 8 * PA + 4];
            }
            #pragma unroll
            for (int j = 0; j < NT; j++) {
                int base = (wn + j * 8 + gr) * PB + g * 8 + tc;
                bf[j][0] = Bs[base];
                bf[j][1] = Bs[base + 4];
            }
            #pragma unroll
            for (int i = 0; i < MT; i++)
                #pragma unroll
                for (int j = 0; j < NT; j++)
                    mma_tf32(acc[i][j], af[i], bf[j]);
        }
        __syncthreads();
        if (!more) break;
    }

    // ---- epilogue ----
    #pragma unroll
    for (int i = 0; i < MT; i++) {
        #pragma unroll
        for (int j = 0; j < NT; j++) {
            int row0 = bm + wm + i * 16 + gr;
            int col  = bn + wn + j * 8 + 2 * tc;
            float* p0 = C + (size_t)row0 * ldc + col;
            float* p1 = C + (size_t)(row0 + 8) * ldc + col;
            float2 v0 = make_float2(acc[i][j][0] * scale, acc[i][j][1] * scale);
            float2 v1 = make_float2(acc[i][j][2] * scale, acc[i][j][3] * scale);
            if (ACCUM) {
                float2 o0 = *(const float2*)p0, o1 = *(const float2*)p1;
                v0.x += o0.x; v0.y += o0.y; v1.x += o1.x; v1.y += o1.y;
            }
            *(float2*)p0 = v0;
            *(float2*)p1 = v1;
        }
    }
}

// ---------------------------- kernel wrappers ------------------------------
template <bool ACCUM>
__global__ void __launch_bounds__(256, 1)
gemm_tc_kernel(float* __restrict__ C, const float* __restrict__ A,
               const float* __restrict__ B, int K, int lda, int ldb, int ldc) {
    gemm_core<128, 128, 2, 4, ACCUM, false>(C, A, B, K, lda, ldb, ldc, 1.0f);
}

// dots[bh][i][j] = SCALE * sum_d q[b,i,h,d]*k[b,j,h,d]; z>=64 -> sigma path
__global__ void __launch_bounds__(256, 1)
dots_tc_kernel() {
    const int z = blockIdx.z;
    const float* qkv = (z >= BH_) ? g_sg_qkv : g_mu_qkv;
    float* dots      = (z >= BH_) ? g_sg_dots : g_mu_dots;
    const int bh = z & (BH_ - 1);
    const int b = bh >> 4, h = bh & 15;
    const float* A  = qkv + (size_t)b * N_ * QKV_ + h * DH_;
    const float* Bq = A + D_;
    float* C = dots + (size_t)bh * N_ * N_;
    gemm_core<128, 128, 2, 4, false, false>(C, A, Bq, DH_, QKV_, QKV_, N_, SCALE_);
}

// O[b,i,h*64+d] = sum_j attn[bh,i,j] * v[b,j,h,d]  (NN gemm, transposed load)
__global__ void __launch_bounds__(256, 1)
pv_tc_kernel() {
    const int z = blockIdx.z;
    const float* attn = (z >= BH_) ? g_sg_dots : g_mu_dots;
    const float* qkv  = (z >= BH_) ? g_sg_qkv : g_mu_qkv;
    float* O          = (z >= BH_) ? g_sg_o : g_mu_o;
    const int bh = z & (BH_ - 1);
    const int b = bh >> 4, h = bh & 15;
    const float* A = attn + (size_t)bh * N_ * N_;
    const float* V = qkv + (size_t)b * N_ * QKV_ + 2 * D_ + h * DH_;
    float* C = O + (size_t)b * N_ * D_ + h * DH_;
    gemm_core<128, 64, 4, 2, false, true>(C, A, V, N_, N_, QKV_, D_, 1.0f);
}

// ------------------------------ prep weights -------------------------------
__device__ __forceinline__ float softplusf(float x) {
    return fmaxf(x, 0.0f) + log1pf(expf(-fabsf(x)));
}

__global__ void prep_weights_kernel(const float* __restrict__ Wqkv_mu,
                                    const float* __restrict__ Wqkv_raw,
                                    const float* __restrict__ Wout_mu,
                                    const float* __restrict__ Wout_raw) {
    int i = blockIdx.x * blockDim.x + threadIdx.x;
    const int nq = QKV_ * D_;
    if (i < nq) {
        float w = Wqkv_mu[i];
        g_Wqkv_mu2[i] = w * w;
        g_Wqkv_sig[i] = softplusf(Wqkv_raw[i]);
    } else {
        int j = i - nq;
        if (j < D_ * D_) {
            float w = Wout_mu[j];
            g_Wout_mu2[j] = w * w;
            g_Wout_sig[j] = softplusf(Wout_raw[j]);
        }
    }
}

// -------------------------------- layernorm --------------------------------
__global__ void layernorm_kernel(const float* __restrict__ mu,
                                 const float* __restrict__ sigma,
                                 const float* __restrict__ gamma,
                                 const float* __restrict__ beta) {
    const int row = blockIdx.x;
    const int t   = threadIdx.x;
    const float4* mrow = (const float4*)(mu + (size_t)row * D_);
    float4 m = mrow[t];

    float s  = m.x + m.y + m.z + m.w;
    float sq = m.x * m.x + m.y * m.y + m.z * m.z + m.w * m.w;

    __shared__ float red[256];
    red[t] = s; __syncthreads();
    #pragma unroll
    for (int o = 128; o > 0; o >>= 1) { if (t < o) red[t] += red[t + o]; __syncthreads(); }
    float mean = red[0] * (1.0f / D_);
    __syncthreads();
    red[t] = sq; __syncthreads();
    #pragma unroll
    for (int o = 128; o > 0; o >>= 1) { if (t < o) red[t] += red[t + o]; __syncthreads(); }
    float var = red[0] * (1.0f / D_) - mean * mean;
    float inv = rsqrtf(var + 1e-5f);

    const float4 sg = ((const float4*)(sigma + (size_t)row * D_))[t];
    const float4 gm = ((const float4*)gamma)[t];
    const float4 bt = ((const float4*)beta)[t];

    float4 mo, so, m2;
    mo.x = (m.x - mean) * inv * gm.x + bt.x;  so.x = sg.x * gm.x * gm.x * inv * inv;  m2.x = fmaf(mo.x, mo.x, so.x);
    mo.y = (m.y - mean) * inv * gm.y + bt.y;  so.y = sg.y * gm.y * gm.y * inv * inv;  m2.y = fmaf(mo.y, mo.y, so.y);
    mo.z = (m.z - mean) * inv * gm.z + bt.z;  so.z = sg.z * gm.z * gm.z * inv * inv;  m2.z = fmaf(mo.z, mo.z, so.z);
    mo.w = (m.w - mean) * inv * gm.w + bt.w;  so.w = sg.w * gm.w * gm.w * inv * inv;  m2.w = fmaf(mo.w, mo.w, so.w);

    ((float4*)g_mu_n)[(size_t)row * 256 + t] = mo;
    ((float4*)g_sg_n)[(size_t)row * 256 + t] = so;
    ((float4*)g_m2s )[(size_t)row * 256 + t] = m2;
}

// --------------------------------- softmax ---------------------------------
__global__ void softmax_kernel() {
    const size_t row = blockIdx.x;
    float* mrow = g_mu_dots + row * N_;
    float* srow = g_sg_dots + row * N_;
    const int t = threadIdx.x;

    float4 m = ((const float4*)mrow)[t];
    float lm = fmaxf(fmaxf(m.x, m.y), fmaxf(m.z, m.w));

    __shared__ float red[256];
    red[t] = lm; __syncthreads();
    #pragma unroll
    for (int o = 128; o > 0; o >>= 1) { if (t < o) red[t] = fmaxf(red[t], red[t + o]); __syncthreads(); }
    const float rmax = red[0];
    __syncthreads();

    float4 e;
    e.x = expf(m.x - rmax); e.y = expf(m.y - rmax);
    e.z = expf(m.z - rmax); e.w = expf(m.w - rmax);
    red[t] = e.x + e.y + e.z + e.w; __syncthreads();
    #pragma unroll
    for (int o = 128; o > 0; o >>= 1) { if (t < o) red[t] += red[t + o]; __syncthreads(); }
    const float inv = 1.0f / red[0];

    float4 p;
    p.x = e.x * inv; p.y = e.y * inv; p.z = e.z * inv; p.w = e.w * inv;

    float4 sg = ((const float4*)srow)[t];
    float4 so;
    float jx = p.x * (1.0f - p.x); so.x = jx * jx * sg.x;
    float jy = p.y * (1.0f - p.y); so.y = jy * jy * sg.y;
    float jz = p.z * (1.0f - p.z); so.z = jz * jz * sg.z;
    float jw = p.w * (1.0f - p.w); so.w = jw * jw * sg.w;

    ((float4*)mrow)[t] = p;
    ((float4*)srow)[t] = so;
}

// ------------------------------ m2s for output -----------------------------
__global__ void m2so_kernel() {
    int i = blockIdx.x * blockDim.x + threadIdx.x;
    float mo = g_mu_o[i];
    g_m2s_o[i] = fmaf(mo, mo, g_sg_o[i]);
}

// --------------------------------- launch ----------------------------------
extern "C" void kernel_launch(void* const* d_in, const int* in_sizes, int n_in,
                              void* d_out, int out_size) {
    (void)in_sizes; (void)n_in; (void)out_size;
    const float* mu       = (const float*)d_in[0];
    const float* sigma    = (const float*)d_in[1];
    const float* gamma    = (const float*)d_in[2];
    const float* beta     = (const float*)d_in[3];
    const float* Wqkv_mu  = (const float*)d_in[4];
    const float* Wqkv_raw = (const float*)d_in[5];
    const float* Wout_mu  = (const float*)d_in[6];
    const float* Wout_raw = (const float*)d_in[7];
    float* out = (float*)d_out;

    float *p_mu_n, *p_sg_n, *p_m2s, *p_wqs, *p_wq2, *p_wos, *p_wo2;
    float *p_mu_qkv, *p_sg_qkv, *p_mu_o, *p_sg_o, *p_m2so;
    cudaGetSymbolAddress((void**)&p_mu_n,   g_mu_n);
    cudaGetSymbolAddress((void**)&p_sg_n,   g_sg_n);
    cudaGetSymbolAddress((void**)&p_m2s,    g_m2s);
    cudaGetSymbolAddress((void**)&p_wqs,    g_Wqkv_sig);
    cudaGetSymbolAddress((void**)&p_wq2,    g_Wqkv_mu2);
    cudaGetSymbolAddress((void**)&p_wos,    g_Wout_sig);
    cudaGetSymbolAddress((void**)&p_wo2,    g_Wout_mu2);
    cudaGetSymbolAddress((void**)&p_mu_qkv, g_mu_qkv);
    cudaGetSymbolAddress((void**)&p_sg_qkv, g_sg_qkv);
    cudaGetSymbolAddress((void**)&p_mu_o,   g_mu_o);
    cudaGetSymbolAddress((void**)&p_sg_o,   g_sg_o);
    cudaGetSymbolAddress((void**)&p_m2so,   g_m2s_o);

    // 1. weight transforms
    prep_weights_kernel<<<(QKV_ * D_ + D_ * D_ + 255) / 256, 256>>>(
        Wqkv_mu, Wqkv_raw, Wout_mu, Wout_raw);

    // 2. layernorm (+ mu^2+sigma)
    layernorm_kernel<<<M_, 256>>>(mu, sigma, gamma, beta);

    // 3. QKV projections (tensor cores)
    dim3 gq(QKV_ / 128, M_ / 128);
    gemm_tc_kernel<false><<<gq, 256>>>(p_mu_qkv, p_mu_n, Wqkv_mu, D_, D_, D_, QKV_);
    gemm_tc_kernel<false><<<gq, 256>>>(p_sg_qkv, p_m2s,  p_wqs,   D_, D_, D_, QKV_);
    gemm_tc_kernel<true ><<<gq, 256>>>(p_sg_qkv, p_sg_n, p_wq2,   D_, D_, D_, QKV_);

    // 4. attention scores (mu & sg), scaled
    dots_tc_kernel<<<dim3(N_ / 128, N_ / 128, 2 * BH_), 256>>>();

    // 5. softmax + variance Jacobian (in place)
    softmax_kernel<<<BH_ * N_, 256>>>();

    // 6. attn @ V (mu & sg)
    pv_tc_kernel<<<dim3(1, N_ / 128, 2 * BH_), 256>>>();

    // 7. mu_o^2 + sg_o
    m2so_kernel<<<(M_ * D_) / 256, 256>>>();

    // 8. output projection (tensor cores) -> d_out
    dim3 go(D_ / 128, M_ / 128);
    gemm_tc_kernel<false><<<go, 256>>>(out,           p_mu_o, Wout_mu, D_, D_, D_, D_);
    gemm_tc_kernel<false><<<go, 256>>>(out + M_ * D_, p_m2so, p_wos,   D_, D_, D_, D_);
    gemm_tc_kernel<true ><<<go, 256>>>(out + M_ * D_, p_sg_o, p_wo2,   D_, D_, D_, D_);
}

// round 4
// speedup vs baseline: 2.6391x; 1.1230x over previous
#include <cuda_runtime.h>
#include <math.h>
#include <stdint.h>

// ---------------------------------------------------------------------------
// VDP attention, round 3: tf32 mma.sync GEMMs with 3-stage cp.async pipeline.
// tf32 rounding moved to producers (GEMM loops feed raw bits -> exact).
// B=4, N=1024, D=1024, H=16, Dh=64.
// ---------------------------------------------------------------------------

#define B_ 4
#define N_ 1024
#define D_ 1024
#define H_ 16
#define DH_ 64
#define M_ (B_ * N_)       /* 4096 rows */
#define QKV_ (3 * D_)      /* 3072 */
#define BH_ (B_ * H_)      /* 64 */
#define SCALE_ 0.125f      /* 64^-0.5 */

// ------------------------- scratch (static device) -------------------------
__device__ float g_mu_n [M_ * D_];
__device__ float g_sg_n [M_ * D_];
__device__ float g_m2s  [M_ * D_];          // mu_n^2 + sigma_n
__device__ float g_Wqkv_mu_r[QKV_ * D_];    // tf32-rounded copies
__device__ float g_Wqkv_sig[QKV_ * D_];
__device__ float g_Wqkv_mu2[QKV_ * D_];
__device__ float g_Wout_mu_r[D_ * D_];
__device__ float g_Wout_sig[D_ * D_];
__device__ float g_Wout_mu2[D_ * D_];
__device__ float g_mu_qkv[M_ * QKV_];
__device__ float g_sg_qkv[M_ * QKV_];
__device__ float g_mu_dots[BH_ * N_ * N_];  // becomes attn in place
__device__ float g_sg_dots[BH_ * N_ * N_];
__device__ float g_mu_o [M_ * D_];
__device__ float g_sg_o [M_ * D_];
__device__ float g_m2s_o[M_ * D_];          // mu_o^2 + sg_o

// ------------------------------ tf32 helpers -------------------------------
__device__ __forceinline__ uint32_t f2tf32(float f) {
    uint32_t u;
    asm("cvt.rna.tf32.f32 %0, %1;" : "=r"(u) : "f"(f));
    return u;
}
__device__ __forceinline__ float rtf(float f) {
    return __uint_as_float(f2tf32(f));
}

__device__ __forceinline__ void mma_tf32(float c[4], const uint32_t a[4],
                                         const uint32_t b[2]) {
    asm volatile(
        "mma.sync.aligned.m16n8k8.row.col.f32.tf32.tf32.f32 "
        "{%0,%1,%2,%3},{%4,%5,%6,%7},{%8,%9},{%0,%1,%2,%3};"
        : "+f"(c[0]), "+f"(c[1]), "+f"(c[2]), "+f"(c[3])
        : "r"(a[0]), "r"(a[1]), "r"(a[2]), "r"(a[3]), "r"(b[0]), "r"(b[1]));
}

__device__ __forceinline__ void cp16(void* smem_ptr, const void* g) {
    uint32_t s = (uint32_t)__cvta_generic_to_shared(smem_ptr);
    asm volatile("cp.async.cg.shared.global [%0], [%1], 16;\n" :: "r"(s), "l"(g));
}
__device__ __forceinline__ void cp_commit() {
    asm volatile("cp.async.commit_group;\n");
}
template <int N>
__device__ __forceinline__ void cp_wait() {
    asm volatile("cp.async.wait_group %0;\n" :: "n"(N));
}

// ------------------------- pipelined tensor-core GEMM ----------------------
// C[M,N] (+)= scale * A[M,K] * op(B).  op(B)=B[N,K] (BT=false) or B[K,N]
// (BT=true).  BK=32, 3-stage cp.async pipeline, 256 threads, warps WR x WC.
// Inputs are assumed pre-rounded to tf32; MMA consumes raw bits.
template <int BM, int BN, int WR, int WC, bool ACCUM, bool BT, bool RND>
__device__ __forceinline__ void gemm_core(float* __restrict__ C,
                                          const float* __restrict__ A,
                                          const float* __restrict__ Bm,
                                          int K, int lda, int ldb, int ldc,
                                          float scale) {
    constexpr int WM = BM / WR, WN = BN / WC;
    constexpr int MT = WM / 16, NT = WN / 8;
    constexpr int PA = 36;                  // A smem pitch (k-contig rows)
    constexpr int PB = BT ? 72 : 36;        // B pitch (k-major when BT)
    constexpr int ASZ = BM * PA;
    constexpr int BSZ = BT ? 32 * PB : BN * PB;
    constexpr int STG = ASZ + BSZ;
    constexpr int NA = BM * 32 / (256 * 4); // float4 cp.async per thread (A)
    constexpr int NB = BN * 32 / (256 * 4);

    extern __shared__ uint32_t sh[];

    const int tid = threadIdx.x;
    const int bm = blockIdx.y * BM, bn = blockIdx.x * BN;
    const int w = tid >> 5, lane = tid & 31;
    const int gr = lane >> 2, tc = lane & 3;
    const int wm = (w / WC) * WM, wn = (w % WC) * WN;
    const int niter = K / 32;

    auto load_stage = [&](int s, int k0) {
        uint32_t* As = sh + s * STG;
        uint32_t* Bs = As + ASZ;
        #pragma unroll
        for (int r = 0; r < NA; r++) {
            int idx = tid + 256 * r;
            cp16(&As[(idx >> 3) * PA + (idx & 7) * 4],
                 A + (size_t)(bm + (idx >> 3)) * lda + (idx & 7) * 4 + k0);
        }
        #pragma unroll
        for (int r = 0; r < NB; r++) {
            int idx = tid + 256 * r;
            if (BT) {
                int kr = idx / (BN / 4), n0 = (idx % (BN / 4)) * 4;
                cp16(&Bs[kr * PB + n0],
                     Bm + (size_t)(k0 + kr) * ldb + bn + n0);
            } else {
                cp16(&Bs[(idx >> 3) * PB + (idx & 7) * 4],
                     Bm + (size_t)(bn + (idx >> 3)) * ldb + (idx & 7) * 4 + k0);
            }
        }
    };

    float acc[MT][NT][4] = {};

    load_stage(0, 0);
    cp_commit();
    if (niter > 1) load_stage(1, 32);
    cp_commit();

    for (int i = 0; i < niter; i++) {
        cp_wait<1>();
        __syncthreads();
        if (i + 2 < niter) load_stage((i + 2) % 3, (i + 2) * 32);
        cp_commit();

        const uint32_t* As = sh + (i % 3) * STG;
        const uint32_t* Bs = As + ASZ;
        #pragma unroll
        for (int g = 0; g < 4; g++) {
            uint32_t af[MT][4], bf[NT][2];
            #pragma unroll
            for (int ii = 0; ii < MT; ii++) {
                int base = (wm + ii * 16 + gr) * PA + g * 8 + tc;
                af[ii][0] = As[base];
                af[ii][2] = As[base + 4];
                af[ii][1] = As[base + 8 * PA];
                af[ii][3] = As[base + 8 * PA + 4];
            }
            #pragma unroll
            for (int j = 0; j < NT; j++) {
                if (BT) {
                    int n = wn + j * 8 + gr;
                    bf[j][0] = Bs[(g * 8 + tc) * PB + n];
                    bf[j][1] = Bs[(g * 8 + tc + 4) * PB + n];
                } else {
                    int base = (wn + j * 8 + gr) * PB + g * 8 + tc;
                    bf[j][0] = Bs[base];
                    bf[j][1] = Bs[base + 4];
                }
            }
            #pragma unroll
            for (int ii = 0; ii < MT; ii++)
                #pragma unroll
                for (int j = 0; j < NT; j++)
                    mma_tf32(acc[ii][j], af[ii], bf[j]);
        }
        __syncthreads();
    }

    // ---- epilogue ----
    #pragma unroll
    for (int ii = 0; ii < MT; ii++) {
        #pragma unroll
        for (int j = 0; j < NT; j++) {
            int row0 = bm + wm + ii * 16 + gr;
            int col  = bn + wn + j * 8 + 2 * tc;
            float* p0 = C + (size_t)row0 * ldc + col;
            float* p1 = C + (size_t)(row0 + 8) * ldc + col;
            float2 v0 = make_float2(acc[ii][j][0] * scale, acc[ii][j][1] * scale);
            float2 v1 = make_float2(acc[ii][j][2] * scale, acc[ii][j][3] * scale);
            if (ACCUM) {
                float2 o0 = *(const float2*)p0, o1 = *(const float2*)p1;
                v0.x += o0.x; v0.y += o0.y; v1.x += o1.x; v1.y += o1.y;
            }
            if (RND) {
                v0.x = rtf(v0.x); v0.y = rtf(v0.y);
                v1.x = rtf(v1.x); v1.y = rtf(v1.y);
            }
            *(float2*)p0 = v0;
            *(float2*)p1 = v1;
        }
    }
}

// ---------------------------- kernel wrappers ------------------------------
template <bool ACCUM, bool RND>
__global__ void __launch_bounds__(256, 1)
gemm_tc_kernel(float* __restrict__ C, const float* __restrict__ A,
               const float* __restrict__ B, int K, int lda, int ldb, int ldc) {
    gemm_core<128, 128, 2, 4, ACCUM, false, RND>(C, A, B, K, lda, ldb, ldc, 1.0f);
}

__global__ void __launch_bounds__(256, 1)
dots_tc_kernel() {
    const int z = blockIdx.z;
    const float* qkv = (z >= BH_) ? g_sg_qkv : g_mu_qkv;
    float* dots      = (z >= BH_) ? g_sg_dots : g_mu_dots;
    const int bh = z & (BH_ - 1);
    const int b = bh >> 4, h = bh & 15;
    const float* A  = qkv + (size_t)b * N_ * QKV_ + h * DH_;
    const float* Bq = A + D_;
    float* C = dots + (size_t)bh * N_ * N_;
    gemm_core<128, 128, 2, 4, false, false, false>(C, A, Bq, DH_, QKV_, QKV_, N_, SCALE_);
}

__global__ void __launch_bounds__(256, 1)
pv_tc_kernel() {
    const int z = blockIdx.z;
    const float* attn = (z >= BH_) ? g_sg_dots : g_mu_dots;
    const float* qkv  = (z >= BH_) ? g_sg_qkv : g_mu_qkv;
    float* O          = (z >= BH_) ? g_sg_o : g_mu_o;
    const int bh = z & (BH_ - 1);
    const int b = bh >> 4, h = bh & 15;
    const float* A = attn + (size_t)bh * N_ * N_;
    const float* V = qkv + (size_t)b * N_ * QKV_ + 2 * D_ + h * DH_;
    float* C = O + (size_t)b * N_ * D_ + h * DH_;
    gemm_core<128, 64, 4, 2, false, true, true>(C, A, V, N_, N_, QKV_, D_, 1.0f);
}

// ------------------------------ prep weights -------------------------------
__device__ __forceinline__ float softplusf(float x) {
    return fmaxf(x, 0.0f) + log1pf(expf(-fabsf(x)));
}

__global__ void prep_weights_kernel(const float* __restrict__ Wqkv_mu,
                                    const float* __restrict__ Wqkv_raw,
                                    const float* __restrict__ Wout_mu,
                                    const float* __restrict__ Wout_raw) {
    int i = blockIdx.x * blockDim.x + threadIdx.x;
    const int nq = QKV_ * D_;
    if (i < nq) {
        float w = Wqkv_mu[i];
        g_Wqkv_mu_r[i] = rtf(w);
        g_Wqkv_mu2[i] = rtf(w * w);
        g_Wqkv_sig[i] = rtf(softplusf(Wqkv_raw[i]));
    } else {
        int j = i - nq;
        if (j < D_ * D_) {
            float w = Wout_mu[j];
            g_Wout_mu_r[j] = rtf(w);
            g_Wout_mu2[j] = rtf(w * w);
            g_Wout_sig[j] = rtf(softplusf(Wout_raw[j]));
        }
    }
}

// -------------------------------- layernorm --------------------------------
__global__ void layernorm_kernel(const float* __restrict__ mu,
                                 const float* __restrict__ sigma,
                                 const float* __restrict__ gamma,
                                 const float* __restrict__ beta) {
    const int row = blockIdx.x;
    const int t   = threadIdx.x;
    const float4* mrow = (const float4*)(mu + (size_t)row * D_);
    float4 m = mrow[t];

    float s  = m.x + m.y + m.z + m.w;
    float sq = m.x * m.x + m.y * m.y + m.z * m.z + m.w * m.w;

    __shared__ float red[256];
    red[t] = s; __syncthreads();
    #pragma unroll
    for (int o = 128; o > 0; o >>= 1) { if (t < o) red[t] += red[t + o]; __syncthreads(); }
    float mean = red[0] * (1.0f / D_);
    __syncthreads();
    red[t] = sq; __syncthreads();
    #pragma unroll
    for (int o = 128; o > 0; o >>= 1) { if (t < o) red[t] += red[t + o]; __syncthreads(); }
    float var = red[0] * (1.0f / D_) - mean * mean;
    float inv = rsqrtf(var + 1e-5f);

    const float4 sg = ((const float4*)(sigma + (size_t)row * D_))[t];
    const float4 gm = ((const float4*)gamma)[t];
    const float4 bt = ((const float4*)beta)[t];

    float4 mo, so, m2;
    mo.x = (m.x - mean) * inv * gm.x + bt.x;  so.x = sg.x * gm.x * gm.x * inv * inv;  m2.x = fmaf(mo.x, mo.x, so.x);
    mo.y = (m.y - mean) * inv * gm.y + bt.y;  so.y = sg.y * gm.y * gm.y * inv * inv;  m2.y = fmaf(mo.y, mo.y, so.y);
    mo.z = (m.z - mean) * inv * gm.z + bt.z;  so.z = sg.z * gm.z * gm.z * inv * inv;  m2.z = fmaf(mo.z, mo.z, so.z);
    mo.w = (m.w - mean) * inv * gm.w + bt.w;  so.w = sg.w * gm.w * gm.w * inv * inv;  m2.w = fmaf(mo.w, mo.w, so.w);

    mo.x = rtf(mo.x); mo.y = rtf(mo.y); mo.z = rtf(mo.z); mo.w = rtf(mo.w);
    so.x = rtf(so.x); so.y = rtf(so.y); so.z = rtf(so.z); so.w = rtf(so.w);
    m2.x = rtf(m2.x); m2.y = rtf(m2.y); m2.z = rtf(m2.z); m2.w = rtf(m2.w);

    ((float4*)g_mu_n)[(size_t)row * 256 + t] = mo;
    ((float4*)g_sg_n)[(size_t)row * 256 + t] = so;
    ((float4*)g_m2s )[(size_t)row * 256 + t] = m2;
}

// --------------------------------- softmax ---------------------------------
__global__ void softmax_kernel() {
    const size_t row = blockIdx.x;
    float* mrow = g_mu_dots + row * N_;
    float* srow = g_sg_dots + row * N_;
    const int t = threadIdx.x;

    float4 m = ((const float4*)mrow)[t];
    float lm = fmaxf(fmaxf(m.x, m.y), fmaxf(m.z, m.w));

    __shared__ float red[256];
    red[t] = lm; __syncthreads();
    #pragma unroll
    for (int o = 128; o > 0; o >>= 1) { if (t < o) red[t] = fmaxf(red[t], red[t + o]); __syncthreads(); }
    const float rmax = red[0];
    __syncthreads();

    float4 e;
    e.x = __expf(m.x - rmax); e.y = __expf(m.y - rmax);
    e.z = __expf(m.z - rmax); e.w = __expf(m.w - rmax);
    red[t] = e.x + e.y + e.z + e.w; __syncthreads();
    #pragma unroll
    for (int o = 128; o > 0; o >>= 1) { if (t < o) red[t] += red[t + o]; __syncthreads(); }
    const float inv = 1.0f / red[0];

    float4 p;
    p.x = e.x * inv; p.y = e.y * inv; p.z = e.z * inv; p.w = e.w * inv;

    float4 sg = ((const float4*)srow)[t];
    float4 so;
    float jx = p.x * (1.0f - p.x); so.x = rtf(jx * jx * sg.x);
    float jy = p.y * (1.0f - p.y); so.y = rtf(jy * jy * sg.y);
    float jz = p.z * (1.0f - p.z); so.z = rtf(jz * jz * sg.z);
    float jw = p.w * (1.0f - p.w); so.w = rtf(jw * jw * sg.w);
    p.x = rtf(p.x); p.y = rtf(p.y); p.z = rtf(p.z); p.w = rtf(p.w);

    ((float4*)mrow)[t] = p;
    ((float4*)srow)[t] = so;
}

// ------------------------------ m2s for output -----------------------------
__global__ void m2so_kernel() {
    int i = blockIdx.x * blockDim.x + threadIdx.x;
    float mo = g_mu_o[i];
    g_m2s_o[i] = rtf(fmaf(mo, mo, g_sg_o[i]));
}

// --------------------------------- launch ----------------------------------
extern "C" void kernel_launch(void* const* d_in, const int* in_sizes, int n_in,
                              void* d_out, int out_size) {
    (void)in_sizes; (void)n_in; (void)out_size;
    const float* mu       = (const float*)d_in[0];
    const float* sigma    = (const float*)d_in[1];
    const float* gamma    = (const float*)d_in[2];
    const float* beta     = (const float*)d_in[3];
    const float* Wqkv_mu  = (const float*)d_in[4];
    const float* Wqkv_raw = (const float*)d_in[5];
    const float* Wout_mu  = (const float*)d_in[6];
    const float* Wout_raw = (const float*)d_in[7];
    float* out = (float*)d_out;

    float *p_mu_n, *p_sg_n, *p_m2s, *p_wq_r, *p_wqs, *p_wq2, *p_wo_r, *p_wos, *p_wo2;
    float *p_mu_qkv, *p_sg_qkv, *p_mu_o, *p_sg_o, *p_m2so;
    cudaGetSymbolAddress((void**)&p_mu_n,   g_mu_n);
    cudaGetSymbolAddress((void**)&p_sg_n,   g_sg_n);
    cudaGetSymbolAddress((void**)&p_m2s,    g_m2s);
    cudaGetSymbolAddress((void**)&p_wq_r,   g_Wqkv_mu_r);
    cudaGetSymbolAddress((void**)&p_wqs,    g_Wqkv_sig);
    cudaGetSymbolAddress((void**)&p_wq2,    g_Wqkv_mu2);
    cudaGetSymbolAddress((void**)&p_wo_r,   g_Wout_mu_r);
    cudaGetSymbolAddress((void**)&p_wos,    g_Wout_sig);
    cudaGetSymbolAddress((void**)&p_wo2,    g_Wout_mu2);
    cudaGetSymbolAddress((void**)&p_mu_qkv, g_mu_qkv);
    cudaGetSymbolAddress((void**)&p_sg_qkv, g_sg_qkv);
    cudaGetSymbolAddress((void**)&p_mu_o,   g_mu_o);
    cudaGetSymbolAddress((void**)&p_sg_o,   g_sg_o);
    cudaGetSymbolAddress((void**)&p_m2so,   g_m2s_o);

    const int SMEM_BIG = 3 * (128 * 36 + 128 * 36) * 4;   // 110592
    const int SMEM_PV  = 3 * (128 * 36 + 32 * 72) * 4;    // 82944
    cudaFuncSetAttribute(gemm_tc_kernel<false, true>,  cudaFuncAttributeMaxDynamicSharedMemorySize, SMEM_BIG);
    cudaFuncSetAttribute(gemm_tc_kernel<true,  true>,  cudaFuncAttributeMaxDynamicSharedMemorySize, SMEM_BIG);
    cudaFuncSetAttribute(gemm_tc_kernel<false, false>, cudaFuncAttributeMaxDynamicSharedMemorySize, SMEM_BIG);
    cudaFuncSetAttribute(gemm_tc_kernel<true,  false>, cudaFuncAttributeMaxDynamicSharedMemorySize, SMEM_BIG);
    cudaFuncSetAttribute(dots_tc_kernel, cudaFuncAttributeMaxDynamicSharedMemorySize, SMEM_BIG);
    cudaFuncSetAttribute(pv_tc_kernel,   cudaFuncAttributeMaxDynamicSharedMemorySize, SMEM_PV);

    // 1. weight transforms (+ tf32 rounding)
    prep_weights_kernel<<<(QKV_ * D_ + D_ * D_ + 255) / 256, 256>>>(
        Wqkv_mu, Wqkv_raw, Wout_mu, Wout_raw);

    // 2. layernorm (+ mu^2+sigma, tf32 rounded)
    layernorm_kernel<<<M_, 256>>>(mu, sigma, gamma, beta);

    // 3. QKV projections (pipelined tensor cores)
    dim3 gq(QKV_ / 128, M_ / 128);
    gemm_tc_kernel<false, true><<<gq, 256, SMEM_BIG>>>(p_mu_qkv, p_mu_n, p_wq_r, D_, D_, D_, QKV_);
    gemm_tc_kernel<false, true><<<gq, 256, SMEM_BIG>>>(p_sg_qkv, p_m2s,  p_wqs,  D_, D_, D_, QKV_);
    gemm_tc_kernel<true,  true><<<gq, 256, SMEM_BIG>>>(p_sg_qkv, p_sg_n, p_wq2,  D_, D_, D_, QKV_);

    // 4. attention scores (mu & sg), scaled
    dots_tc_kernel<<<dim3(N_ / 128, N_ / 128, 2 * BH_), 256, SMEM_BIG>>>();

    // 5. softmax + variance Jacobian (in place, tf32 rounded)
    softmax_kernel<<<BH_ * N_, 256>>>();

    // 6. attn @ V (mu & sg)
    pv_tc_kernel<<<dim3(1, N_ / 128, 2 * BH_), 256, SMEM_PV>>>();

    // 7. mu_o^2 + sg_o
    m2so_kernel<<<(M_ * D_) / 256, 256>>>();

    // 8. output projection -> d_out (no rounding on final results)
    dim3 go(D_ / 128, M_ / 128);
    gemm_tc_kernel<false, false><<<go, 256, SMEM_BIG>>>(out,           p_mu_o, p_wo_r, D_, D_, D_, D_);
    gemm_tc_kernel<false, false><<<go, 256, SMEM_BIG>>>(out + M_ * D_, p_m2so, p_wos,  D_, D_, D_, D_);
    gemm_tc_kernel<true,  false><<<go, 256, SMEM_BIG>>>(out + M_ * D_, p_sg_o, p_wo2,  D_, D_, D_, D_);
}